// round 1
// baseline (speedup 1.0000x reference)
#include <cuda_runtime.h>

// ---------------- static problem sizes ----------------
#define N_NODES 20000
#define E_EDGES 320000
#define B_Q 4
#define K_T 32
#define D_DIM 32
#define DR_REL 40
#define T_STEPS 10
#define VTH 2.0f
#define DECAY 0.7788007830714049f   // exp(-1/4)
#define RATIO 0.95f
#define NSCALE 8.025261215232422f   // (1 - 0.95^10) / (1 - 0.95)

// ---------------- persistent scratch (no allocs allowed) ----------------
__device__ unsigned g_smask[T_STEPS * N_NODES * B_Q];       // 3.2 MB spike bitmasks
__device__ float    g_v[N_NODES * B_Q * D_DIM];             // 10.24 MB membrane
__device__ float    g_c[N_NODES * B_Q * D_DIM];             // 10.24 MB synapse current
__device__ int      g_rowptr[N_NODES + 1];
__device__ int      g_cnt[N_NODES];
__device__ int      g_csr_src[E_EDGES];
__device__ int      g_csr_type[E_EDGES];
__device__ float    g_wrel[B_Q * DR_REL * D_DIM];           // 20 KB dependent rel weights
__device__ float    g_query[B_Q * D_DIM];

// ---------------- prologue: query gather + dependent relation weights ----------------
// w_rel[b, r, d] = relw_b[r*D+d] + sum_i query[b,i] * relw_W[i, r*D+d]
__global__ void prologue_kernel(const int* __restrict__ r_index,
                                const float* __restrict__ query_emb,
                                const float* __restrict__ relw_W,
                                const float* __restrict__ relw_b) {
    int id = blockIdx.x * blockDim.x + threadIdx.x;
    if (id >= B_Q * DR_REL * D_DIM) return;
    int b  = id / (DR_REL * D_DIM);
    int rd = id % (DR_REL * D_DIM);
    const float* q = query_emb + r_index[b] * D_DIM;
    float acc = relw_b[rd];
#pragma unroll
    for (int i = 0; i < D_DIM; ++i)
        acc += q[i] * relw_W[i * (DR_REL * D_DIM) + rd];
    g_wrel[id] = acc;
    if (rd < D_DIM) g_query[b * D_DIM + rd] = q[rd];
}

// ---------------- initial LIF state + s_mask[0] ----------------
__global__ void init_kernel(const int* __restrict__ h_index) {
    int tid = blockIdx.x * blockDim.x + threadIdx.x;   // exact grid: N*B*D threads
    int d = tid & 31;
    int b = (tid >> 5) & (B_Q - 1);
    int n = tid / (B_Q * D_DIM);
    float boundary = 0.f;
    if (n == h_index[b]) {
        float q = g_query[b * D_DIM + d];
        boundary = q * (VTH * 0.5f) + VTH * 0.5f;
    }
    bool sp = (boundary - VTH) >= 0.f;
    g_v[tid] = sp ? 0.f : boundary;
    g_c[tid] = 0.f;
    unsigned m = __ballot_sync(0xffffffffu, sp);
    if (d == 0) g_smask[n * B_Q + b] = m;   // t = 0 slice
}

// ---------------- CSR-by-dst construction ----------------
__global__ void zero_cnt_kernel() {
    int i = blockIdx.x * blockDim.x + threadIdx.x;
    if (i < N_NODES) g_cnt[i] = 0;
}

__global__ void count_kernel(const int* __restrict__ edge_dst) {
    int e = blockIdx.x * blockDim.x + threadIdx.x;
    if (e < E_EDGES) atomicAdd(&g_cnt[edge_dst[e]], 1);
}

__global__ void scan_kernel() {
    __shared__ int ssum[1024];
    const int CH = (N_NODES + 1023) / 1024;   // 20
    int tid = threadIdx.x;
    int base = tid * CH;
    int vals[CH];
    int s = 0;
#pragma unroll
    for (int i = 0; i < CH; ++i) {
        int idx = base + i;
        int v = (idx < N_NODES) ? g_cnt[idx] : 0;
        vals[i] = s;
        s += v;
    }
    ssum[tid] = s;
    __syncthreads();
    for (int off = 1; off < 1024; off <<= 1) {
        int t = (tid >= off) ? ssum[tid - off] : 0;
        __syncthreads();
        ssum[tid] += t;
        __syncthreads();
    }
    int excl = (tid == 0) ? 0 : ssum[tid - 1];
#pragma unroll
    for (int i = 0; i < CH; ++i) {
        int idx = base + i;
        if (idx < N_NODES) {
            int p = excl + vals[i];
            g_rowptr[idx] = p;
            g_cnt[idx]    = p;   // reuse as write cursor
        }
    }
    if (tid == 1023) g_rowptr[N_NODES] = ssum[1023];
}

__global__ void fill_kernel(const int* __restrict__ edge_src,
                            const int* __restrict__ edge_dst,
                            const int* __restrict__ edge_type) {
    int e = blockIdx.x * blockDim.x + threadIdx.x;
    if (e >= E_EDGES) return;
    int pos = atomicAdd(&g_cnt[edge_dst[e]], 1);
    g_csr_src[pos]  = edge_src[e];
    g_csr_type[pos] = edge_type[e];
}

// ---------------- one LIF time step: gather + linear + dynamics ----------------
// warp = one (node, batch); lane = feature d
__global__ __launch_bounds__(512) void step_kernel(int t,
                                                   const float* __restrict__ lin_W,
                                                   const float* __restrict__ lin_b) {
    __shared__ float s_WT[D_DIM * D_DIM];   // s_WT[i*32+j] = lin_W[j*32+i]
    __shared__ float s_lb[D_DIM];
    int tid = threadIdx.x;
    for (int i = tid; i < D_DIM * D_DIM; i += blockDim.x) {
        int ii = i >> 5, j = i & 31;
        s_WT[i] = lin_W[j * D_DIM + ii];
    }
    if (tid < D_DIM) s_lb[tid] = lin_b[tid];
    __syncthreads();

    int warp_g = (blockIdx.x * blockDim.x + tid) >> 5;
    int lane = tid & 31;
    int n = warp_g >> 2;          // / B_Q
    int b = warp_g & (B_Q - 1);

    int beg = g_rowptr[n];
    int end = g_rowptr[n + 1];
    const unsigned* __restrict__ mprev = g_smask + (size_t)(t - 1) * (N_NODES * B_Q);
    const float* __restrict__ wr = g_wrel + b * (DR_REL * D_DIM);

    float agg = 0.f;
    for (int j = beg; j < end; ++j) {
        int src = g_csr_src[j];
        unsigned m = mprev[src * B_Q + b];
        if (m) {  // warp-uniform: skip dead sources entirely
            int ty = g_csr_type[j];
            if ((m >> lane) & 1u) agg += wr[ty * D_DIM + lane];
        }
    }

    // x[j] = lin_b[j] + sum_i agg_i * lin_W[j, i]
    float x = s_lb[lane];
#pragma unroll
    for (int i = 0; i < D_DIM; ++i)
        x += __shfl_sync(0xffffffffu, agg, i) * s_WT[i * D_DIM + lane];

    int idx = (n * B_Q + b) * D_DIM + lane;
    float c = g_c[idx] * DECAY + x;
    float v = g_v[idx] * DECAY + c;
    bool sp = (v - VTH) >= 0.f;
    g_c[idx] = c;
    g_v[idx] = sp ? 0.f : v;
    unsigned bm = __ballot_sync(0xffffffffu, sp);
    if (lane == 0) g_smask[(size_t)t * (N_NODES * B_Q) + n * B_Q + b] = bm;
}

// ---------------- readout: temporal kernel + 2-layer MLP ----------------
// one 64-thread block per (b, k)
__global__ void score_kernel(const int* __restrict__ t_index,
                             const float* __restrict__ W1,
                             const float* __restrict__ b1,
                             const float* __restrict__ W2,
                             const float* __restrict__ b2,
                             float* __restrict__ out) {
    int b = blockIdx.x / K_T;
    int k = blockIdx.x % K_T;
    int j = threadIdx.x;   // 0..63
    __shared__ float feat[2 * D_DIM];
    __shared__ float hsh[2 * D_DIM];

    int tn = t_index[b * K_T + k];
    if (j < D_DIM) {
        float e = 0.f;
        float w = 1.0f;
#pragma unroll
        for (int t = 0; t < T_STEPS; ++t) {
            unsigned m = g_smask[(size_t)t * (N_NODES * B_Q) + tn * B_Q + b];
            if ((m >> j) & 1u) e += w;
            w *= RATIO;
        }
        feat[j] = e / NSCALE;
    } else {
        feat[j] = g_query[b * D_DIM + (j - D_DIM)];
    }
    __syncthreads();

    float acc = b1[j];
#pragma unroll
    for (int i = 0; i < 2 * D_DIM; ++i)
        acc += feat[i] * W1[j * (2 * D_DIM) + i];
    hsh[j] = fmaxf(acc, 0.f) * W2[j];
    __syncthreads();

    if (j < 32) {
        float v = hsh[j] + hsh[j + 32];
#pragma unroll
        for (int off = 16; off; off >>= 1)
            v += __shfl_down_sync(0xffffffffu, v, off);
        if (j == 0) out[b * K_T + k] = v + b2[0];
    }
}

// ---------------- launch ----------------
extern "C" void kernel_launch(void* const* d_in, const int* in_sizes, int n_in,
                              void* d_out, int out_size) {
    const int*   edge_src  = (const int*)d_in[0];
    const int*   edge_dst  = (const int*)d_in[1];
    const int*   edge_type = (const int*)d_in[2];
    const int*   h_index   = (const int*)d_in[3];
    const int*   t_index   = (const int*)d_in[4];
    const int*   r_index   = (const int*)d_in[5];
    const float* query_emb = (const float*)d_in[6];
    const float* relw_W    = (const float*)d_in[7];
    const float* relw_b    = (const float*)d_in[8];
    const float* lin_W     = (const float*)d_in[9];
    const float* lin_b     = (const float*)d_in[10];
    const float* mlp_W1    = (const float*)d_in[11];
    const float* mlp_b1    = (const float*)d_in[12];
    const float* mlp_W2    = (const float*)d_in[13];
    const float* mlp_b2    = (const float*)d_in[14];
    float* out = (float*)d_out;

    prologue_kernel<<<(B_Q * DR_REL * D_DIM + 255) / 256, 256>>>(r_index, query_emb, relw_W, relw_b);
    init_kernel<<<(N_NODES * B_Q * D_DIM) / 256, 256>>>(h_index);

    zero_cnt_kernel<<<(N_NODES + 255) / 256, 256>>>();
    count_kernel<<<(E_EDGES + 255) / 256, 256>>>(edge_dst);
    scan_kernel<<<1, 1024>>>();
    fill_kernel<<<(E_EDGES + 255) / 256, 256>>>(edge_src, edge_dst, edge_type);

    for (int t = 1; t < T_STEPS; ++t)
        step_kernel<<<(N_NODES * B_Q * D_DIM) / 512, 512>>>(t, lin_W, lin_b);

    score_kernel<<<B_Q * K_T, 2 * D_DIM>>>(t_index, mlp_W1, mlp_b1, mlp_W2, mlp_b2, out);
}

// round 2
// speedup vs baseline: 1.7133x; 1.7133x over previous
#include <cuda_runtime.h>

// ---------------- static problem sizes ----------------
#define N_NODES 20000
#define E_EDGES 320000
#define B_Q 4
#define K_T 32
#define D_DIM 32
#define DR_REL 40
#define T_STEPS 10
#define VTH 2.0f
#define DECAY 0.7788007830714049f   // exp(-1/4)
#define RATIO 0.95f
#define NSCALE 8.025261215232422f   // (1 - 0.95^10) / (1 - 0.95)

// ---------------- persistent scratch (no allocs allowed) ----------------
__device__ unsigned g_smask[T_STEPS * N_NODES * B_Q];       // 3.2 MB spike bitmasks
__device__ float    g_v[N_NODES * B_Q * D_DIM];             // 10.24 MB membrane
__device__ float    g_c[N_NODES * B_Q * D_DIM];             // 10.24 MB synapse current
__device__ int      g_rowptr[N_NODES + 1];
__device__ int      g_cnt[N_NODES];
__device__ unsigned g_csr_packed[E_EDGES];                  // src | (type << 16)
__device__ float    g_wrel[B_Q * DR_REL * D_DIM];           // 20 KB dependent rel weights
__device__ float    g_query[B_Q * D_DIM];

// ---------------- prologue: query gather + dependent relation weights ----------------
__global__ void prologue_kernel(const int* __restrict__ r_index,
                                const float* __restrict__ query_emb,
                                const float* __restrict__ relw_W,
                                const float* __restrict__ relw_b) {
    int id = blockIdx.x * blockDim.x + threadIdx.x;
    if (id >= B_Q * DR_REL * D_DIM) return;
    int b  = id / (DR_REL * D_DIM);
    int rd = id % (DR_REL * D_DIM);
    const float* q = query_emb + r_index[b] * D_DIM;
    float acc = relw_b[rd];
#pragma unroll
    for (int i = 0; i < D_DIM; ++i)
        acc += q[i] * relw_W[i * (DR_REL * D_DIM) + rd];
    g_wrel[id] = acc;
    if (rd < D_DIM) g_query[b * D_DIM + rd] = q[rd];
}

// ---------------- initial LIF state + s_mask[0] ----------------
__global__ void init_kernel(const int* __restrict__ h_index) {
    int tid = blockIdx.x * blockDim.x + threadIdx.x;   // exact grid: N*B*D threads
    int d = tid & 31;
    int b = (tid >> 5) & (B_Q - 1);
    int n = tid / (B_Q * D_DIM);
    float boundary = 0.f;
    if (n == h_index[b]) {
        float q = g_query[b * D_DIM + d];
        boundary = q * (VTH * 0.5f) + VTH * 0.5f;
    }
    bool sp = (boundary - VTH) >= 0.f;
    g_v[tid] = sp ? 0.f : boundary;
    g_c[tid] = 0.f;
    unsigned m = __ballot_sync(0xffffffffu, sp);
    if (d == 0) g_smask[n * B_Q + b] = m;   // t = 0 slice
}

// ---------------- CSR-by-dst construction ----------------
__global__ void zero_cnt_kernel() {
    int i = blockIdx.x * blockDim.x + threadIdx.x;
    if (i < N_NODES) g_cnt[i] = 0;
}

__global__ void count_kernel(const int* __restrict__ edge_dst) {
    int e = blockIdx.x * blockDim.x + threadIdx.x;
    if (e < E_EDGES) atomicAdd(&g_cnt[edge_dst[e]], 1);
}

__global__ void scan_kernel() {
    __shared__ int ssum[1024];
    const int CH = (N_NODES + 1023) / 1024;   // 20
    int tid = threadIdx.x;
    int base = tid * CH;
    int vals[CH];
    int s = 0;
#pragma unroll
    for (int i = 0; i < CH; ++i) {
        int idx = base + i;
        int v = (idx < N_NODES) ? g_cnt[idx] : 0;
        vals[i] = s;
        s += v;
    }
    ssum[tid] = s;
    __syncthreads();
    for (int off = 1; off < 1024; off <<= 1) {
        int t = (tid >= off) ? ssum[tid - off] : 0;
        __syncthreads();
        ssum[tid] += t;
        __syncthreads();
    }
    int excl = (tid == 0) ? 0 : ssum[tid - 1];
#pragma unroll
    for (int i = 0; i < CH; ++i) {
        int idx = base + i;
        if (idx < N_NODES) {
            int p = excl + vals[i];
            g_rowptr[idx] = p;
            g_cnt[idx]    = p;   // reuse as write cursor
        }
    }
    if (tid == 1023) g_rowptr[N_NODES] = ssum[1023];
}

__global__ void fill_kernel(const int* __restrict__ edge_src,
                            const int* __restrict__ edge_dst,
                            const int* __restrict__ edge_type) {
    int e = blockIdx.x * blockDim.x + threadIdx.x;
    if (e >= E_EDGES) return;
    int pos = atomicAdd(&g_cnt[edge_dst[e]], 1);
    g_csr_packed[pos] = (unsigned)edge_src[e] | ((unsigned)edge_type[e] << 16);
}

// ---------------- one LIF time step: gather + linear + dynamics ----------------
// warp = one node, all 4 batches; lane = feature d
__global__ __launch_bounds__(256) void step_kernel(int t,
                                                   const float* __restrict__ lin_W,
                                                   const float* __restrict__ lin_b) {
    __shared__ float s_WT[D_DIM * D_DIM];   // s_WT[i*32+lane] = lin_W[lane*32+i]
    int tid = threadIdx.x;
    for (int i = tid; i < D_DIM * D_DIM; i += 256) {
        int ii = i >> 5, j = i & 31;
        s_WT[i] = lin_W[j * D_DIM + ii];
    }
    __syncthreads();

    int n = (blockIdx.x * 256 + tid) >> 5;     // exact: 2500 blocks * 8 warps = 20000
    int lane = tid & 31;

    int beg = g_rowptr[n];
    int end = g_rowptr[n + 1];
    const unsigned* __restrict__ mprev = g_smask + (size_t)(t - 1) * (N_NODES * B_Q);

    float a0 = 0.f, a1 = 0.f, a2 = 0.f, a3 = 0.f;
#pragma unroll 4
    for (int j = beg; j < end; ++j) {
        unsigned p = __ldg(g_csr_packed + j);
        int src = p & 0xffffu;
        uint4 m = *reinterpret_cast<const uint4*>(mprev + src * 4);
        if (m.x | m.y | m.z | m.w) {           // warp-uniform skip
            int off = (int)(p >> 16) * D_DIM + lane;
            if ((m.x >> lane) & 1u) a0 += __ldg(g_wrel + off);
            if ((m.y >> lane) & 1u) a1 += __ldg(g_wrel + 1 * DR_REL * D_DIM + off);
            if ((m.z >> lane) & 1u) a2 += __ldg(g_wrel + 2 * DR_REL * D_DIM + off);
            if ((m.w >> lane) & 1u) a3 += __ldg(g_wrel + 3 * DR_REL * D_DIM + off);
        }
    }

    // x[b][lane] = lin_b[lane] + sum_i a_b[i] * lin_W[lane][i]
    float lb = __ldg(lin_b + lane);
    float x0 = lb, x1 = lb, x2 = lb, x3 = lb;
#pragma unroll
    for (int i = 0; i < D_DIM; ++i) {
        float w = s_WT[i * D_DIM + lane];
        x0 = fmaf(__shfl_sync(0xffffffffu, a0, i), w, x0);
        x1 = fmaf(__shfl_sync(0xffffffffu, a1, i), w, x1);
        x2 = fmaf(__shfl_sync(0xffffffffu, a2, i), w, x2);
        x3 = fmaf(__shfl_sync(0xffffffffu, a3, i), w, x3);
    }

    unsigned bm0, bm1, bm2, bm3;
    size_t base = (size_t)n * (B_Q * D_DIM) + lane;
    {
        float c = g_c[base + 0 * D_DIM] * DECAY + x0;
        float v = g_v[base + 0 * D_DIM] * DECAY + c;
        bool sp = (v - VTH) >= 0.f;
        g_c[base + 0 * D_DIM] = c;
        g_v[base + 0 * D_DIM] = sp ? 0.f : v;
        bm0 = __ballot_sync(0xffffffffu, sp);
    }
    {
        float c = g_c[base + 1 * D_DIM] * DECAY + x1;
        float v = g_v[base + 1 * D_DIM] * DECAY + c;
        bool sp = (v - VTH) >= 0.f;
        g_c[base + 1 * D_DIM] = c;
        g_v[base + 1 * D_DIM] = sp ? 0.f : v;
        bm1 = __ballot_sync(0xffffffffu, sp);
    }
    {
        float c = g_c[base + 2 * D_DIM] * DECAY + x2;
        float v = g_v[base + 2 * D_DIM] * DECAY + c;
        bool sp = (v - VTH) >= 0.f;
        g_c[base + 2 * D_DIM] = c;
        g_v[base + 2 * D_DIM] = sp ? 0.f : v;
        bm2 = __ballot_sync(0xffffffffu, sp);
    }
    {
        float c = g_c[base + 3 * D_DIM] * DECAY + x3;
        float v = g_v[base + 3 * D_DIM] * DECAY + c;
        bool sp = (v - VTH) >= 0.f;
        g_c[base + 3 * D_DIM] = c;
        g_v[base + 3 * D_DIM] = sp ? 0.f : v;
        bm3 = __ballot_sync(0xffffffffu, sp);
    }
    if (lane == 0)
        *reinterpret_cast<uint4*>(g_smask + (size_t)t * (N_NODES * B_Q) + n * B_Q) =
            make_uint4(bm0, bm1, bm2, bm3);
}

// ---------------- readout: temporal kernel + 2-layer MLP ----------------
__global__ void score_kernel(const int* __restrict__ t_index,
                             const float* __restrict__ W1,
                             const float* __restrict__ b1,
                             const float* __restrict__ W2,
                             const float* __restrict__ b2,
                             float* __restrict__ out) {
    int b = blockIdx.x / K_T;
    int k = blockIdx.x % K_T;
    int j = threadIdx.x;   // 0..63
    __shared__ float feat[2 * D_DIM];
    __shared__ float hsh[2 * D_DIM];

    int tn = t_index[b * K_T + k];
    if (j < D_DIM) {
        float e = 0.f;
        float w = 1.0f;
#pragma unroll
        for (int t = 0; t < T_STEPS; ++t) {
            unsigned m = g_smask[(size_t)t * (N_NODES * B_Q) + tn * B_Q + b];
            if ((m >> j) & 1u) e += w;
            w *= RATIO;
        }
        feat[j] = e / NSCALE;
    } else {
        feat[j] = g_query[b * D_DIM + (j - D_DIM)];
    }
    __syncthreads();

    float acc = b1[j];
#pragma unroll
    for (int i = 0; i < 2 * D_DIM; ++i)
        acc += feat[i] * W1[j * (2 * D_DIM) + i];
    hsh[j] = fmaxf(acc, 0.f) * W2[j];
    __syncthreads();

    if (j < 32) {
        float v = hsh[j] + hsh[j + 32];
#pragma unroll
        for (int off = 16; off; off >>= 1)
            v += __shfl_down_sync(0xffffffffu, v, off);
        if (j == 0) out[b * K_T + k] = v + b2[0];
    }
}

// ---------------- launch ----------------
extern "C" void kernel_launch(void* const* d_in, const int* in_sizes, int n_in,
                              void* d_out, int out_size) {
    const int*   edge_src  = (const int*)d_in[0];
    const int*   edge_dst  = (const int*)d_in[1];
    const int*   edge_type = (const int*)d_in[2];
    const int*   h_index   = (const int*)d_in[3];
    const int*   t_index   = (const int*)d_in[4];
    const int*   r_index   = (const int*)d_in[5];
    const float* query_emb = (const float*)d_in[6];
    const float* relw_W    = (const float*)d_in[7];
    const float* relw_b    = (const float*)d_in[8];
    const float* lin_W     = (const float*)d_in[9];
    const float* lin_b     = (const float*)d_in[10];
    const float* mlp_W1    = (const float*)d_in[11];
    const float* mlp_b1    = (const float*)d_in[12];
    const float* mlp_W2    = (const float*)d_in[13];
    const float* mlp_b2    = (const float*)d_in[14];
    float* out = (float*)d_out;

    prologue_kernel<<<(B_Q * DR_REL * D_DIM + 255) / 256, 256>>>(r_index, query_emb, relw_W, relw_b);
    init_kernel<<<(N_NODES * B_Q * D_DIM) / 256, 256>>>(h_index);

    zero_cnt_kernel<<<(N_NODES + 255) / 256, 256>>>();
    count_kernel<<<(E_EDGES + 255) / 256, 256>>>(edge_dst);
    scan_kernel<<<1, 1024>>>();
    fill_kernel<<<(E_EDGES + 255) / 256, 256>>>(edge_src, edge_dst, edge_type);

    for (int t = 1; t < T_STEPS; ++t)
        step_kernel<<<N_NODES / 8, 256>>>(t, lin_W, lin_b);

    score_kernel<<<B_Q * K_T, 2 * D_DIM>>>(t_index, mlp_W1, mlp_b1, mlp_W2, mlp_b2, out);
}

// round 3
// speedup vs baseline: 9.9342x; 5.7984x over previous
#include <cuda_runtime.h>

// ---------------- static problem sizes ----------------
#define N_NODES 20000
#define E_EDGES 320000
#define B_Q 4
#define K_T 32
#define D_DIM 32
#define DR_REL 40
#define T_STEPS 10
#define VTH 2.0f
#define DECAY 0.7788007830714049f   // exp(-1/4)
#define RATIO 0.95f
#define NSCALE 8.025261215232422f   // (1 - 0.95^10) / (1 - 0.95)

#define NBD (N_NODES * B_Q * D_DIM)     // 2,560,000 floats

// ---------------- persistent scratch (no allocs allowed) ----------------
__device__ unsigned g_smask[T_STEPS * N_NODES * B_Q];   // 3.2 MB spike bitmasks (zeroed per launch)
__device__ float    g_v[NBD];                           // membrane (zeroed per launch)
__device__ float    g_c[NBD];                           // synapse current (zeroed per launch)
__device__ float    g_agg[NBD];                         // per-step message accumulator
__device__ int      g_hot_flag[N_NODES];
__device__ int      g_hot_list[N_NODES];
__device__ int      g_hot_count;
__device__ int      g_front_count[T_STEPS];             // #spiking nodes per step
__device__ float    g_wrel[B_Q * DR_REL * D_DIM];       // dependent relation weights
__device__ float    g_query[B_Q * D_DIM];

// ---------------- fused zeroing of all per-launch state ----------------
__global__ void zero_kernel() {
    int i = blockIdx.x * blockDim.x + threadIdx.x;      // float4 index
    const float4 z4 = make_float4(0.f, 0.f, 0.f, 0.f);
    const int nbd4 = NBD / 4;                           // 640,000
    if (i < nbd4) {
        reinterpret_cast<float4*>(g_v)[i]   = z4;
        reinterpret_cast<float4*>(g_c)[i]   = z4;
        reinterpret_cast<float4*>(g_agg)[i] = z4;
    }
    const int sm4 = (T_STEPS * N_NODES * B_Q) / 4;      // 200,000
    if (i < sm4) reinterpret_cast<uint4*>(g_smask)[i] = make_uint4(0u, 0u, 0u, 0u);
    if (i < N_NODES / 4) reinterpret_cast<int4*>(g_hot_flag)[i] = make_int4(0, 0, 0, 0);
    if (i == 0) {
        g_hot_count = 0;
#pragma unroll
        for (int t = 0; t < T_STEPS; ++t) g_front_count[t] = 0;
    }
}

// ---------------- prologue: query gather + dependent relation weights ----------------
__global__ void prologue_kernel(const int* __restrict__ r_index,
                                const float* __restrict__ query_emb,
                                const float* __restrict__ relw_W,
                                const float* __restrict__ relw_b) {
    int id = blockIdx.x * blockDim.x + threadIdx.x;
    if (id >= B_Q * DR_REL * D_DIM) return;
    int b  = id / (DR_REL * D_DIM);
    int rd = id % (DR_REL * D_DIM);
    const float* q = query_emb + r_index[b] * D_DIM;
    float acc = relw_b[rd];
#pragma unroll
    for (int i = 0; i < D_DIM; ++i)
        acc += q[i] * relw_W[i * (DR_REL * D_DIM) + rd];
    g_wrel[id] = acc;
    if (rd < D_DIM) g_query[b * D_DIM + rd] = q[rd];
}

// ---------------- initial state: only the B head nodes are nonzero ----------------
// one warp per batch b
__global__ void init_spike_kernel(const int* __restrict__ h_index) {
    int b = threadIdx.x >> 5;
    if (b >= B_Q) return;
    int lane = threadIdx.x & 31;
    int n = h_index[b];
    float q = g_query[b * D_DIM + lane];
    float boundary = q * (VTH * 0.5f) + VTH * 0.5f;
    bool sp = (boundary - VTH) >= 0.f;
    g_v[(n * B_Q + b) * D_DIM + lane] = sp ? 0.f : boundary;
    unsigned m = __ballot_sync(0xffffffffu, sp);
    if (lane == 0) {
        g_smask[n * B_Q + b] = m;
        if (m) atomicAdd(&g_front_count[0], 1);
        // add to hot list (dedupe across batches)
        if (atomicExch(&g_hot_flag[n], 1) == 0) {
            int p = atomicAdd(&g_hot_count, 1);
            g_hot_list[p] = n;
        }
    }
}

// ---------------- message scatter (edge-parallel, frontier-gated) ----------------
// warp per edge (grid-strided); lane = feature d
__global__ __launch_bounds__(256) void msg_kernel(int t,
                                                  const int* __restrict__ edge_src,
                                                  const int* __restrict__ edge_dst,
                                                  const int* __restrict__ edge_type) {
    if (g_front_count[t - 1] == 0) return;   // empty frontier: no messages anywhere
    const unsigned* __restrict__ mp = g_smask + (size_t)(t - 1) * (N_NODES * B_Q);
    int gw = (blockIdx.x * 256 + threadIdx.x) >> 5;
    int lane = threadIdx.x & 31;
    int nw = gridDim.x * 8;
    for (int e = gw; e < E_EDGES; e += nw) {
        int src = edge_src[e];
        uint4 m = *reinterpret_cast<const uint4*>(mp + src * 4);
        if (m.x | m.y | m.z | m.w) {
            int dst = edge_dst[e];
            int ty  = edge_type[e];
            if (lane == 0) {
                if (atomicExch(&g_hot_flag[dst], 1) == 0) {
                    int p = atomicAdd(&g_hot_count, 1);
                    g_hot_list[p] = dst;
                }
            }
            int off = ty * D_DIM + lane;
            float* ag = g_agg + (size_t)(dst * B_Q) * D_DIM + lane;
            if ((m.x >> lane) & 1u) atomicAdd(ag + 0 * D_DIM, g_wrel[0 * DR_REL * D_DIM + off]);
            if ((m.y >> lane) & 1u) atomicAdd(ag + 1 * D_DIM, g_wrel[1 * DR_REL * D_DIM + off]);
            if ((m.z >> lane) & 1u) atomicAdd(ag + 2 * D_DIM, g_wrel[2 * DR_REL * D_DIM + off]);
            if ((m.w >> lane) & 1u) atomicAdd(ag + 3 * D_DIM, g_wrel[3 * DR_REL * D_DIM + off]);
        }
    }
}

// ---------------- LIF update over the hot list only ----------------
// warp per hot node (grid-strided); lane = feature d
__global__ __launch_bounds__(256) void update_kernel(int t,
                                                     const float* __restrict__ lin_W,
                                                     const float* __restrict__ lin_b) {
    int nh = g_hot_count;
    if ((int)(blockIdx.x * 8) >= nh) return;     // whole block has no work
    __shared__ float s_WT[D_DIM * D_DIM];        // s_WT[i*32+j] = lin_W[j*32+i]
    int tid = threadIdx.x;
    for (int i = tid; i < D_DIM * D_DIM; i += 256) {
        int ii = i >> 5, j = i & 31;
        s_WT[i] = lin_W[j * D_DIM + ii];
    }
    __syncthreads();

    int lane = tid & 31;
    float lb = __ldg(lin_b + lane);
    int stride = gridDim.x * 8;

    for (int i = (blockIdx.x * 256 + tid) >> 5; i < nh; i += stride) {
        int n = g_hot_list[i];
        size_t base = (size_t)(n * B_Q) * D_DIM + lane;
        float a0 = g_agg[base + 0 * D_DIM];
        float a1 = g_agg[base + 1 * D_DIM];
        float a2 = g_agg[base + 2 * D_DIM];
        float a3 = g_agg[base + 3 * D_DIM];
        g_agg[base + 0 * D_DIM] = 0.f;           // clean for next step
        g_agg[base + 1 * D_DIM] = 0.f;
        g_agg[base + 2 * D_DIM] = 0.f;
        g_agg[base + 3 * D_DIM] = 0.f;

        float x0 = lb, x1 = lb, x2 = lb, x3 = lb;
#pragma unroll
        for (int k = 0; k < D_DIM; ++k) {
            float w = s_WT[k * D_DIM + lane];
            x0 = fmaf(__shfl_sync(0xffffffffu, a0, k), w, x0);
            x1 = fmaf(__shfl_sync(0xffffffffu, a1, k), w, x1);
            x2 = fmaf(__shfl_sync(0xffffffffu, a2, k), w, x2);
            x3 = fmaf(__shfl_sync(0xffffffffu, a3, k), w, x3);
        }

        unsigned bm[4];
        float xs[4] = {x0, x1, x2, x3};
#pragma unroll
        for (int b = 0; b < B_Q; ++b) {
            float c = g_c[base + b * D_DIM] * DECAY + xs[b];
            float v = g_v[base + b * D_DIM] * DECAY + c;
            bool sp = (v - VTH) >= 0.f;
            g_c[base + b * D_DIM] = c;
            g_v[base + b * D_DIM] = sp ? 0.f : v;
            bm[b] = __ballot_sync(0xffffffffu, sp);
        }
        if (lane == 0) {
            *reinterpret_cast<uint4*>(g_smask + (size_t)t * (N_NODES * B_Q) + n * B_Q) =
                make_uint4(bm[0], bm[1], bm[2], bm[3]);
            if (bm[0] | bm[1] | bm[2] | bm[3]) atomicAdd(&g_front_count[t], 1);
        }
    }
}

// ---------------- readout: temporal kernel + 2-layer MLP ----------------
__global__ void score_kernel(const int* __restrict__ t_index,
                             const float* __restrict__ W1,
                             const float* __restrict__ b1,
                             const float* __restrict__ W2,
                             const float* __restrict__ b2,
                             float* __restrict__ out) {
    int b = blockIdx.x / K_T;
    int k = blockIdx.x % K_T;
    int j = threadIdx.x;   // 0..63
    __shared__ float feat[2 * D_DIM];
    __shared__ float hsh[2 * D_DIM];

    int tn = t_index[b * K_T + k];
    if (j < D_DIM) {
        float e = 0.f;
        float w = 1.0f;
#pragma unroll
        for (int t = 0; t < T_STEPS; ++t) {
            unsigned m = g_smask[(size_t)t * (N_NODES * B_Q) + tn * B_Q + b];
            if ((m >> j) & 1u) e += w;
            w *= RATIO;
        }
        feat[j] = e / NSCALE;
    } else {
        feat[j] = g_query[b * D_DIM + (j - D_DIM)];
    }
    __syncthreads();

    float acc = b1[j];
#pragma unroll
    for (int i = 0; i < 2 * D_DIM; ++i)
        acc += feat[i] * W1[j * (2 * D_DIM) + i];
    hsh[j] = fmaxf(acc, 0.f) * W2[j];
    __syncthreads();

    if (j < 32) {
        float v = hsh[j] + hsh[j + 32];
#pragma unroll
        for (int off = 16; off; off >>= 1)
            v += __shfl_down_sync(0xffffffffu, v, off);
        if (j == 0) out[b * K_T + k] = v + b2[0];
    }
}

// ---------------- launch ----------------
extern "C" void kernel_launch(void* const* d_in, const int* in_sizes, int n_in,
                              void* d_out, int out_size) {
    const int*   edge_src  = (const int*)d_in[0];
    const int*   edge_dst  = (const int*)d_in[1];
    const int*   edge_type = (const int*)d_in[2];
    const int*   h_index   = (const int*)d_in[3];
    const int*   t_index   = (const int*)d_in[4];
    const int*   r_index   = (const int*)d_in[5];
    const float* query_emb = (const float*)d_in[6];
    const float* relw_W    = (const float*)d_in[7];
    const float* relw_b    = (const float*)d_in[8];
    const float* lin_W     = (const float*)d_in[9];
    const float* lin_b     = (const float*)d_in[10];
    const float* mlp_W1    = (const float*)d_in[11];
    const float* mlp_b1    = (const float*)d_in[12];
    const float* mlp_W2    = (const float*)d_in[13];
    const float* mlp_b2    = (const float*)d_in[14];
    float* out = (float*)d_out;

    zero_kernel<<<(NBD / 4 + 255) / 256, 256>>>();
    prologue_kernel<<<(B_Q * DR_REL * D_DIM + 255) / 256, 256>>>(r_index, query_emb, relw_W, relw_b);
    init_spike_kernel<<<1, B_Q * 32>>>(h_index);

    for (int t = 1; t < T_STEPS; ++t) {
        msg_kernel<<<256, 256>>>(t, edge_src, edge_dst, edge_type);
        update_kernel<<<320, 256>>>(t, lin_W, lin_b);
    }

    score_kernel<<<B_Q * K_T, 2 * D_DIM>>>(t_index, mlp_W1, mlp_b1, mlp_W2, mlp_b2, out);
}

// round 4
// speedup vs baseline: 18.0180x; 1.8137x over previous
#include <cuda_runtime.h>

// ---------------- static problem sizes ----------------
#define N_NODES 20000
#define E_EDGES 320000
#define B_Q 4
#define K_T 32
#define D_DIM 32
#define DR_REL 40
#define T_STEPS 10
#define VTH 2.0f
#define DECAY 0.7788007830714049f   // exp(-1/4)
#define RATIO 0.95f
#define NSCALE 8.025261215232422f   // (1 - 0.95^10) / (1 - 0.95)

#define NBLK 112
#define NTHR 256
#define NWARPS (NBLK * NTHR / 32)   // 896 warps

// ---------------- persistent state (zero-initialized; cleanup restores zeros) ----------------
__device__ unsigned g_smask[T_STEPS * N_NODES * B_Q];   // spike bitmasks (sparse-touched)
__device__ float    g_v[N_NODES * B_Q * D_DIM];         // membrane        (sparse-touched)
__device__ float    g_c[N_NODES * B_Q * D_DIM];         // synapse current (sparse-touched)
__device__ float    g_agg[N_NODES * B_Q * D_DIM];       // msg accumulator (sparse-touched)
__device__ int      g_hot_flag[N_NODES];
__device__ int      g_hot_list[N_NODES];
__device__ int      g_hot_count;
__device__ int      g_front_count[T_STEPS];
__device__ float    g_wrel[B_Q * DR_REL * D_DIM];
__device__ float    g_query[B_Q * D_DIM];

// software grid barrier
__device__ unsigned          g_bar_arrive;
__device__ volatile unsigned g_bar_gen;

__device__ __forceinline__ void grid_barrier() {
    __threadfence();            // flush this thread's prior writes to L2
    __syncthreads();
    if (threadIdx.x == 0) {
        unsigned gen = g_bar_gen;
        if (atomicAdd(&g_bar_arrive, 1u) == NBLK - 1u) {
            g_bar_arrive = 0u;
            __threadfence();
            g_bar_gen = gen + 1u;
        } else {
            while (g_bar_gen == gen) __nanosleep(64);
        }
    }
    __syncthreads();
}

__global__ __launch_bounds__(NTHR, 1)
void fused_kernel(const int* __restrict__ edge_src,
                  const int* __restrict__ edge_dst,
                  const int* __restrict__ edge_type,
                  const int* __restrict__ h_index,
                  const int* __restrict__ t_index,
                  const int* __restrict__ r_index,
                  const float* __restrict__ query_emb,
                  const float* __restrict__ relw_W,
                  const float* __restrict__ relw_b,
                  const float* __restrict__ lin_W,
                  const float* __restrict__ lin_b,
                  const float* __restrict__ W1,
                  const float* __restrict__ b1,
                  const float* __restrict__ W2,
                  const float* __restrict__ b2,
                  float* __restrict__ out) {
    __shared__ float s_WT[D_DIM * D_DIM];     // s_WT[i*32+j] = lin_W[j*32+i]
    __shared__ float s_feat[2 * D_DIM];
    __shared__ float s_hsh[2 * D_DIM];

    const int tid   = threadIdx.x;
    const int lane  = tid & 31;
    const int gwarp = (blockIdx.x * NTHR + tid) >> 5;

    // ---------- phase 0: prologue (rel weights + query), s_WT, head-node init ----------
    {
        int id = blockIdx.x * NTHR + tid;
        if (id < B_Q * DR_REL * D_DIM) {
            int b  = id / (DR_REL * D_DIM);
            int rd = id % (DR_REL * D_DIM);
            const float* q = query_emb + r_index[b] * D_DIM;
            float acc = relw_b[rd];
#pragma unroll
            for (int i = 0; i < D_DIM; ++i)
                acc += q[i] * relw_W[i * (DR_REL * D_DIM) + rd];
            g_wrel[id] = acc;
            if (rd < D_DIM) g_query[b * D_DIM + rd] = q[rd];
        }
        for (int i = tid; i < D_DIM * D_DIM; i += NTHR) {
            int ii = i >> 5, j = i & 31;
            s_WT[i] = lin_W[j * D_DIM + ii];
        }
        if (blockIdx.x == 0 && tid < B_Q * 32) {
            int b = tid >> 5;
            int n = h_index[b];
            float q = query_emb[r_index[b] * D_DIM + lane];
            float boundary = q * (VTH * 0.5f) + VTH * 0.5f;
            bool sp = (boundary - VTH) >= 0.f;
            g_v[(n * B_Q + b) * D_DIM + lane] = sp ? 0.f : boundary;
            unsigned m = __ballot_sync(0xffffffffu, sp);
            if (lane == 0) {
                g_smask[n * B_Q + b] = m;
                if (m) atomicAdd(&g_front_count[0], 1);
                if (atomicExch(&g_hot_flag[n], 1) == 0) {
                    int p = atomicAdd(&g_hot_count, 1);
                    g_hot_list[p] = n;
                }
            }
        }
    }
    grid_barrier();

    // ---------- time loop ----------
    const float lb = __ldg(lin_b + lane);
    for (int t = 1; t < T_STEPS; ++t) {
        int fc = __ldcg(&g_front_count[t - 1]);   // grid-uniform (post-barrier)
        if (fc != 0) {
            // message scatter: grid-strided warps over edges
            const unsigned* mp = g_smask + (size_t)(t - 1) * (N_NODES * B_Q);
            for (int e = gwarp; e < E_EDGES; e += NWARPS) {
                int src = __ldg(edge_src + e);
                uint4 m = *reinterpret_cast<const uint4*>(mp + src * 4);
                if (m.x | m.y | m.z | m.w) {
                    int dst = __ldg(edge_dst + e);
                    int ty  = __ldg(edge_type + e);
                    if (lane == 0) {
                        if (atomicExch(&g_hot_flag[dst], 1) == 0) {
                            int p = atomicAdd(&g_hot_count, 1);
                            g_hot_list[p] = dst;
                        }
                    }
                    int off = ty * D_DIM + lane;
                    float* ag = g_agg + (size_t)(dst * B_Q) * D_DIM + lane;
                    if ((m.x >> lane) & 1u) atomicAdd(ag + 0 * D_DIM, __ldg(g_wrel + 0 * DR_REL * D_DIM + off));
                    if ((m.y >> lane) & 1u) atomicAdd(ag + 1 * D_DIM, __ldg(g_wrel + 1 * DR_REL * D_DIM + off));
                    if ((m.z >> lane) & 1u) atomicAdd(ag + 2 * D_DIM, __ldg(g_wrel + 2 * DR_REL * D_DIM + off));
                    if ((m.w >> lane) & 1u) atomicAdd(ag + 3 * D_DIM, __ldg(g_wrel + 3 * DR_REL * D_DIM + off));
                }
            }
            grid_barrier();
        }

        // LIF update over hot list (owner-warp stable: list is append-only)
        int nh = __ldcg(&g_hot_count);
        for (int i = gwarp; i < nh; i += NWARPS) {
            int n = __ldcg(&g_hot_list[i]);
            size_t base = (size_t)(n * B_Q) * D_DIM + lane;
            float a0 = 0.f, a1 = 0.f, a2 = 0.f, a3 = 0.f;
            if (fc != 0) {                        // agg untouched when frontier empty
                a0 = __ldcg(&g_agg[base + 0 * D_DIM]);
                a1 = __ldcg(&g_agg[base + 1 * D_DIM]);
                a2 = __ldcg(&g_agg[base + 2 * D_DIM]);
                a3 = __ldcg(&g_agg[base + 3 * D_DIM]);
                g_agg[base + 0 * D_DIM] = 0.f;
                g_agg[base + 1 * D_DIM] = 0.f;
                g_agg[base + 2 * D_DIM] = 0.f;
                g_agg[base + 3 * D_DIM] = 0.f;
            }
            float x0 = lb, x1 = lb, x2 = lb, x3 = lb;
#pragma unroll
            for (int k = 0; k < D_DIM; ++k) {
                float w = s_WT[k * D_DIM + lane];
                x0 = fmaf(__shfl_sync(0xffffffffu, a0, k), w, x0);
                x1 = fmaf(__shfl_sync(0xffffffffu, a1, k), w, x1);
                x2 = fmaf(__shfl_sync(0xffffffffu, a2, k), w, x2);
                x3 = fmaf(__shfl_sync(0xffffffffu, a3, k), w, x3);
            }
            unsigned bm[4];
            float xs[4] = {x0, x1, x2, x3};
#pragma unroll
            for (int b = 0; b < B_Q; ++b) {
                float c = g_c[base + b * D_DIM] * DECAY + xs[b];
                float v = g_v[base + b * D_DIM] * DECAY + c;
                bool sp = (v - VTH) >= 0.f;
                g_c[base + b * D_DIM] = c;
                g_v[base + b * D_DIM] = sp ? 0.f : v;
                bm[b] = __ballot_sync(0xffffffffu, sp);
            }
            if (lane == 0) {
                *reinterpret_cast<uint4*>(g_smask + (size_t)t * (N_NODES * B_Q) + n * B_Q) =
                    make_uint4(bm[0], bm[1], bm[2], bm[3]);
                if (bm[0] | bm[1] | bm[2] | bm[3]) atomicAdd(&g_front_count[t], 1);
            }
        }
        grid_barrier();
    }

    // ---------- score: temporal kernel + 2-layer MLP, blocks grid-stride over (b,k) ----------
    for (int p = blockIdx.x; p < B_Q * K_T; p += NBLK) {
        int b = p >> 5;             // / K_T
        int k = p & 31;
        int j = tid;
        if (j < 2 * D_DIM) {
            int tn = __ldg(t_index + b * K_T + k);
            if (j < D_DIM) {
                float e = 0.f, w = 1.0f;
#pragma unroll
                for (int t = 0; t < T_STEPS; ++t) {
                    unsigned m = __ldcg(&g_smask[(size_t)t * (N_NODES * B_Q) + tn * B_Q + b]);
                    if ((m >> j) & 1u) e += w;
                    w *= RATIO;
                }
                s_feat[j] = e / NSCALE;
            } else {
                s_feat[j] = g_query[b * D_DIM + (j - D_DIM)];
            }
        }
        __syncthreads();
        if (j < 2 * D_DIM) {
            float acc = __ldg(b1 + j);
#pragma unroll
            for (int i = 0; i < 2 * D_DIM; ++i)
                acc += s_feat[i] * __ldg(W1 + j * (2 * D_DIM) + i);
            s_hsh[j] = fmaxf(acc, 0.f) * __ldg(W2 + j);
        }
        __syncthreads();
        if (j < 32) {
            float v = s_hsh[j] + s_hsh[j + 32];
#pragma unroll
            for (int off = 16; off; off >>= 1)
                v += __shfl_down_sync(0xffffffffu, v, off);
            if (j == 0) out[b * K_T + k] = v + __ldg(b2);
        }
        __syncthreads();
    }
    grid_barrier();   // score must finish reading state before cleanup clobbers it

    // ---------- cleanup: restore pristine zero state for next replay ----------
    {
        int nh = __ldcg(&g_hot_count);
        for (int i = gwarp; i < nh; i += NWARPS) {
            int n = __ldcg(&g_hot_list[i]);
            size_t base = (size_t)(n * B_Q) * D_DIM + lane;
#pragma unroll
            for (int b = 0; b < B_Q; ++b) {
                g_v[base + b * D_DIM] = 0.f;
                g_c[base + b * D_DIM] = 0.f;
                g_agg[base + b * D_DIM] = 0.f;
            }
            if (lane < T_STEPS)
                *reinterpret_cast<uint4*>(g_smask + (size_t)lane * (N_NODES * B_Q) + n * B_Q) =
                    make_uint4(0u, 0u, 0u, 0u);
            if (lane == 0) g_hot_flag[n] = 0;
        }
        if (blockIdx.x == 0 && tid == 0) {
            g_hot_count = 0;
#pragma unroll
            for (int t = 0; t < T_STEPS; ++t) g_front_count[t] = 0;
        }
    }
}

// ---------------- launch ----------------
extern "C" void kernel_launch(void* const* d_in, const int* in_sizes, int n_in,
                              void* d_out, int out_size) {
    fused_kernel<<<NBLK, NTHR>>>(
        (const int*)d_in[0], (const int*)d_in[1], (const int*)d_in[2],
        (const int*)d_in[3], (const int*)d_in[4], (const int*)d_in[5],
        (const float*)d_in[6], (const float*)d_in[7], (const float*)d_in[8],
        (const float*)d_in[9], (const float*)d_in[10],
        (const float*)d_in[11], (const float*)d_in[12],
        (const float*)d_in[13], (const float*)d_in[14],
        (float*)d_out);
}